// round 12
// baseline (speedup 1.0000x reference)
#include <cuda_runtime.h>
#include <math.h>

#define CHUNK    256
#define MAXA     262144
#define NCELLS   1024

// Per-(image,gt) max IoU as float bits in uint (IoU >= 0 -> uint max == float max).
__device__ unsigned int g_highest[256];
// Counting-sort scratch (k_gtmax candidate filtering only)
__device__ int    g_hist[NCELLS];
__device__ int    g_base[NCELLS];
__device__ int    g_cursor[NCELLS];
__device__ float4 g_sanch[MAXA];     // spatially sorted anchors (order irrelevant)

__device__ __forceinline__ float box_area(const float4 b) {
    return __fmul_rn(__fsub_rn(b.z, b.x), __fsub_rn(b.w, b.y));
}

// 2*max(x,0) via FADD with |src| modifier (fma pipe, not alu FMNMX).
__device__ __forceinline__ float relu2(float x) {
    return __fadd_rn(x, fabsf(x));
}

// inter4 = 4 * fl(clip-product) — exactly 4x the reference inter (pow2 scale
// commutes with round-to-nearest).
__device__ __forceinline__ float inter4_of(const float4 g, const float4 a) {
    const float ww2 = relu2(__fsub_rn(fminf(g.z, a.z), fmaxf(g.x, a.x)));
    const float hh2 = relu2(__fsub_rn(fminf(g.w, a.w), fmaxf(g.y, a.y)));
    return __fmul_rn(ww2, hh2);
}

// exact unscaled inter (lq rescan path — must match reference bits)
__device__ __forceinline__ float inter_of(const float4 g, const float4 a) {
    const float ww = fmaxf(__fsub_rn(fminf(g.z, a.z), fmaxf(g.x, a.x)), 0.0f);
    const float hh = fmaxf(__fsub_rn(fminf(g.w, a.w), fmaxf(g.y, a.y)), 0.0f);
    return __fmul_rn(ww, hh);
}

__device__ __forceinline__ float sqrt_approx(float x) {
    float r; asm("sqrt.approx.f32 %0, %1;" : "=f"(r) : "f"(x)); return r;
}

// Exact product comparison x1*y1 > x2*y2 (FMA error term): grouping/order-
// independent max in k_gtmax (determinism across graph replays + vs sorting).
__device__ __forceinline__ bool prod_gt(float x1, float y1, float x2, float y2) {
    const float p1 = __fmul_rn(x1, y1);
    const float p2 = __fmul_rn(x2, y2);
    const float e1 = __fmaf_rn(x1, y1, -p1);
    const float e2 = __fmaf_rn(x2, y2, -p2);
    return (p1 > p2) || ((p1 == p2) && (e1 > e2));
}

// bucket key: 32x16 spatial cells (by anchor center) x 2 size classes.
__device__ __forceinline__ int cell_key(const float4 a) {
    const float cx = 0.5f * (a.x + a.z);
    const float cy = 0.5f * (a.y + a.w);
    int ix = (int)(cx * (32.0f / 1333.0f));
    int iy = (int)(cy * (16.0f / 800.0f));
    ix = max(0, min(31, ix));
    iy = max(0, min(15, iy));
    const int s = (fmaxf(a.z - a.x, a.w - a.y) > 136.0f) ? 1 : 0;
    return ((iy * 32 + ix) << 1) | s;
}

// positive-overlap test (conservative: bbox contains every chunk anchor, so
// no overlap with bbox => inter == 0 for every anchor of the chunk)
__device__ __forceinline__ bool overlap_pos(const float4 bb, const float4 g) {
    return (fminf(bb.z, g.z) > fmaxf(bb.x, g.x)) &&
           (fminf(bb.w, g.w) > fmaxf(bb.y, g.y));
}

// ---------------------------------------------------------------------------
__global__ void k_hist(const float4* __restrict__ anchors, int A) {
    const int i = blockIdx.x * 256 + threadIdx.x;
    if (i < A) atomicAdd(&g_hist[cell_key(anchors[i])], 1);
}

__global__ void k_scan() {   // 1 block, 1024 threads: exclusive scan
    __shared__ int s[NCELLS];
    const int t = threadIdx.x;
    const int own = g_hist[t];
    s[t] = own;
    __syncthreads();
    for (int off = 1; off < NCELLS; off <<= 1) {
        const int v = (t >= off) ? s[t - off] : 0;
        __syncthreads();
        s[t] += v;
        __syncthreads();
    }
    g_base[t] = s[t] - own;
}

__global__ void k_scatter(const float4* __restrict__ anchors, int A, int Apad) {
    const int i = blockIdx.x * 256 + threadIdx.x;
    if (i < A) {
        const float4 a = anchors[i];
        const int key  = cell_key(a);
        const int slot = g_base[key] + atomicAdd(&g_cursor[key], 1);
        g_sanch[slot] = a;
    } else if (i < Apad) {   // padding: far-away degenerate anchors (iou == 0)
        g_sanch[i] = make_float4(-3.0e6f, -3.0e6f, -3.0e6f + 1.0f, -3.0e6f + 1.0f);
    }
}

// ---------------------------------------------------------------------------
// Kernel 1: highest_per_gt over sorted chunks, with fused per-chunk bbox
// reduction and candidate (b,g) compaction. Exact Dekker compare -> the max
// is independent of anchor grouping; one correctly-rounded __fdiv_rn per
// candidate then atomicMax (fl monotone => equals reference per-gt max).
// ---------------------------------------------------------------------------
__global__ __launch_bounds__(256) void k_gtmax(
    const float4* __restrict__ gt, int B)
{
    __shared__ float4 sanch[CHUNK];
    __shared__ float  sarea[CHUNK];
    __shared__ float4 sbb[8];
    __shared__ short  slist[256];
    __shared__ int    scnt;

    const int c    = blockIdx.x;
    const int tid  = threadIdx.x;
    const int lane = tid & 31;
    const int warp = tid >> 5;

    if (tid == 0) scnt = 0;
    float4 a4;
    {
        a4 = g_sanch[c * CHUNK + tid];
        sanch[tid] = a4;
        sarea[tid] = box_area(a4);
    }
    // fused chunk-bbox: warp shuffle reduce, then warp0 over 8 partials
    float4 m = a4;
#pragma unroll
    for (int off = 16; off > 0; off >>= 1) {
        m.x = fminf(m.x, __shfl_xor_sync(0xffffffffu, m.x, off));
        m.y = fminf(m.y, __shfl_xor_sync(0xffffffffu, m.y, off));
        m.z = fmaxf(m.z, __shfl_xor_sync(0xffffffffu, m.z, off));
        m.w = fmaxf(m.w, __shfl_xor_sync(0xffffffffu, m.w, off));
    }
    if (lane == 0) sbb[warp] = m;
    __syncthreads();
    if (tid < 32) {
        float4 bbf = sbb[0];
        if (tid < 8) bbf = sbb[tid];
#pragma unroll
        for (int off = 4; off > 0; off >>= 1) {
            bbf.x = fminf(bbf.x, __shfl_xor_sync(0xffffffffu, bbf.x, off));
            bbf.y = fminf(bbf.y, __shfl_xor_sync(0xffffffffu, bbf.y, off));
            bbf.z = fmaxf(bbf.z, __shfl_xor_sync(0xffffffffu, bbf.z, off));
            bbf.w = fmaxf(bbf.w, __shfl_xor_sync(0xffffffffu, bbf.w, off));
        }
        if (tid == 0) sbb[0] = bbf;
    }
    __syncthreads();

    // candidate (b,g) compaction vs chunk bbox
    const float4 bb = sbb[0];
    const int nbg = B * 32;           // <= 256
    bool cand = false;
    if (tid < nbg) cand = overlap_pos(bb, gt[tid]);
    const unsigned vm = __ballot_sync(0xffffffffu, cand);
    if (cand) {
        const int leader = __ffs(vm) - 1;
        const int rank = __popc(vm & ((1u << lane) - 1u));
        int base = 0;
        if (lane == leader) base = atomicAdd(&scnt, __popc(vm));
        base = __shfl_sync(vm, base, leader);
        slist[base + rank] = (short)tid;
    }
    __syncthreads();

    const int ncand = scnt;
    const int ngroups = (ncand + 31) >> 5;
    const float4 dead = make_float4(-3.0e6f, -3.0e6f, -3.0e6f + 1.0f, -3.0e6f + 1.0f);
    const int j0 = warp * 32;

    for (int k = 0; k < ngroups; k++) {
        const int li = k * 32 + lane;
        const int bg = (li < ncand) ? (int)slist[li] : -1;
        const float4 gg = (bg >= 0) ? gt[bg] : dead;
        const float areag = box_area(gg);

        float bi4 = 0.0f, bS = 1.0f;
#pragma unroll 8
        for (int j = j0; j < j0 + 32; j++) {
            const float4 aa = sanch[j];               // warp-broadcast LDS
            const float S      = __fadd_rn(areag, sarea[j]);
            const float inter4 = inter4_of(gg, aa);
            const bool upd = prod_gt(inter4, bS, bi4, S);  // exact compare
            bi4 = upd ? inter4 : bi4;
            bS  = upd ? S      : bS;
        }
        if (bg >= 0) {
            const float bi = __fmul_rn(bi4, 0.25f);   // exact unscale (pow2)
            const float h  = __fdiv_rn(bi, __fsub_rn(bS, bi));
            atomicMax(&g_highest[bg], __float_as_uint(h));
        }
    }
}

// ---------------------------------------------------------------------------
// Kernel 2 (R9 best version, untouched): per (image, anchor) labeling +
// matched box + centerness on ORIGINAL anchor order — fully coalesced I/O.
// ---------------------------------------------------------------------------
__global__ __launch_bounds__(256) void k_label(
    const float4* __restrict__ anchors,
    const float4* __restrict__ gt,
    float* __restrict__ out,
    int A, int B)
{
    __shared__ float4 sgt[32];    // gt box
    __shared__ float2 sax[32];    // {area_g, 4*h'}
    __shared__ float  s_h[32];    // exact global max per gt
    __shared__ int    s_anyz;     // any gt with h == 0 -> lq for ALL anchors

    const int b = blockIdx.y;
    if (threadIdx.x < 32) {
        const float4 g4 = gt[b * 32 + threadIdx.x];
        sgt[threadIdx.x] = g4;
        const float h = __uint_as_float(g_highest[b * 32 + threadIdx.x]);
        s_h[threadIdx.x] = h;
        float hp4;
        if (h > 0.0f) {
            const float hl = h * 0.99999f;
            hp4 = (hl / (1.0f + hl)) * 0.99999f * 4.0f;   // threshold for inter4
        } else {
            hp4 = __int_as_float(0x7f800000);  // +inf: band never fires
        }
        sax[threadIdx.x] = make_float2(box_area(g4), hp4);
        const unsigned zb = __ballot_sync(0xffffffffu, h == 0.0f);
        if (threadIdx.x == 0) s_anyz = (zb != 0u);
    }
    __syncthreads();

    const int a = blockIdx.x * 256 + threadIdx.x;
    if (a >= A) return;

    const float4 a4   = anchors[a];
    const float areaa = box_area(a4);

    float bi4 = 0.0f, bS = 1.0f;  // running exact-ratio max as (4*inter, S)
    int   bidx = 0;
    float band = -1.0f;           // >= 0 iff some gt may satisfy iou == h

#pragma unroll
    for (int g = 0; g < 32; g++) {
        const float4 g4 = sgt[g];
        const float2 ax = sax[g];
        const float S      = __fadd_rn(ax.x, areaa);
        const float inter4 = inter4_of(g4, a4);

        const bool upd = __fmul_rn(inter4, bS) > __fmul_rn(bi4, S);
        bi4  = upd ? inter4 : bi4;
        bS   = upd ? S      : bS;
        bidx = upd ? g      : bidx;

        band = fmaxf(band, __fmaf_rn(S, -ax.y, inter4));
    }

    bool lq = (s_anyz != 0);
    if (band >= 0.0f) {           // rare (~0.13% of threads)
#pragma unroll 4
        for (int g = 0; g < 32; g++) {
            const float S     = __fadd_rn(sax[g].x, areaa);
            const float inter = inter_of(sgt[g], a4);
            const float uni   = __fsub_rn(S, inter);
            lq = lq || (__fdiv_rn(inter, uni) == s_h[g]);
        }
    }

    const float bi  = __fmul_rn(bi4, 0.25f);          // exact unscale
    const float val = __fdividef(bi, __fsub_rn(bS, bi));
    const float glf = (lq || val >= 0.7f) ? 1.0f : ((val >= 0.3f) ? -1.0f : 0.0f);
    const float olf = (lq || val >= 0.3f) ? 1.0f : ((val >= 0.1f) ? -1.0f : 0.0f);

    const float4 tb4 = sgt[bidx];            // matched gt box (shared argmax)

    const float cx = 0.5f * (a4.x + a4.z);
    const float cy = 0.5f * (a4.y + a4.w);
    const float w  = a4.z - a4.x;
    const float hg = a4.w - a4.y;
    const float nl = cx - tb4.x;
    const float nr = tb4.z - cx;
    const float nt = cy - tb4.y;
    const float nb = tb4.w - cy;

    float cent = 0.0f;
    if (olf != 0.0f && nl >= 0.0f && nr >= 0.0f && nt >= 0.0f && nb >= 0.0f) {
        const float rx = __fdividef(fminf(nl, nr),
                                    __fmaf_rn(1e-12f, w,  fmaxf(nl, nr)));
        const float ry = __fdividef(fminf(nt, nb),
                                    __fmaf_rn(1e-12f, hg, fmaxf(nt, nb)));
        const float prod = rx * ry;
        cent = (prod > 0.0f) ? sqrt_approx(prod) : 0.0f;
    }

    // layout: [gt_labels B*A][matched B*A*4][obj_labels B*A][centerness B*A]
    const size_t BA = (size_t)B * (size_t)A;
    const size_t o  = (size_t)b * (size_t)A + (size_t)a;

    out[o] = glf;
    reinterpret_cast<float4*>(out + BA)[o] = tb4;
    out[BA * 5 + o] = olf;
    out[BA * 6 + o] = cent;
}

extern "C" void kernel_launch(void* const* d_in, const int* in_sizes, int n_in,
                              void* d_out, int out_size)
{
    const float4* gt      = (const float4*)d_in[0];   // [B,32,4] f32
    const float4* anchors = (const float4*)d_in[1];   // [A,4]    f32
    const int B = in_sizes[0] / (32 * 4);
    const int A = in_sizes[1] / 4;
    float* out = (float*)d_out;

    const int nchunk = (A + CHUNK - 1) / CHUNK;
    const int Apad   = nchunk * CHUNK;

    void *ph = nullptr, *pc = nullptr, *pg = nullptr;
    cudaGetSymbolAddress(&ph, g_hist);
    cudaGetSymbolAddress(&pc, g_cursor);
    cudaGetSymbolAddress(&pg, g_highest);
    cudaMemsetAsync(ph, 0, NCELLS * sizeof(int), 0);
    cudaMemsetAsync(pc, 0, NCELLS * sizeof(int), 0);
    cudaMemsetAsync(pg, 0, 256 * sizeof(unsigned int), 0);

    k_hist<<<(A + 255) / 256, 256>>>(anchors, A);
    k_scan<<<1, NCELLS>>>();
    k_scatter<<<(Apad + 255) / 256, 256>>>(anchors, A, Apad);
    k_gtmax<<<nchunk, 256>>>(gt, B);

    dim3 g2((A + 255) / 256, B);
    k_label<<<g2, 256>>>(anchors, gt, out, A, B);
}

// round 13
// speedup vs baseline: 1.5565x; 1.5565x over previous
#include <cuda_runtime.h>
#include <math.h>

// Per-(image,gt) max IoU (rounded quotient, reference semantics via rounding
// monotonicity), stored as float bits in uint (IoU >= 0 -> uint max == float max).
__device__ unsigned int g_highest[256];

__device__ __forceinline__ float box_area(const float4 b) {
    return __fmul_rn(__fsub_rn(b.z, b.x), __fsub_rn(b.w, b.y));
}

// 2*max(x,0) via FADD with |src| modifier (fma pipe, not alu FMNMX).
__device__ __forceinline__ float relu2(float x) {
    return __fadd_rn(x, fabsf(x));
}

// inter4 = 4 * fl(clip-product) — exactly 4x the reference inter (pow2 scale
// commutes with round-to-nearest; no overflow: areas < 1e6).
__device__ __forceinline__ float inter4_of(const float4 g, const float4 a) {
    const float ww2 = relu2(__fsub_rn(fminf(g.z, a.z), fmaxf(g.x, a.x)));
    const float hh2 = relu2(__fsub_rn(fminf(g.w, a.w), fmaxf(g.y, a.y)));
    return __fmul_rn(ww2, hh2);
}

// exact unscaled inter (lq rescan path — must match reference bits)
__device__ __forceinline__ float inter_of(const float4 g, const float4 a) {
    const float ww = fmaxf(__fsub_rn(fminf(g.z, a.z), fmaxf(g.x, a.x)), 0.0f);
    const float hh = fmaxf(__fsub_rn(fminf(g.w, a.w), fmaxf(g.y, a.y)), 0.0f);
    return __fmul_rn(ww, hh);
}

__device__ __forceinline__ float sqrt_approx(float x) {
    float r; asm("sqrt.approx.f32 %0, %1;" : "=f"(r) : "f"(x)); return r;
}

// ---------------------------------------------------------------------------
// Kernel 1 (R9 version): highest_per_gt[b][g]. One block = one 256-anchor
// chunk shared by ALL images: warp = image, lane = gt. Branch-free running
// max of the exact ratio inter/S on 4x-scaled inter (scale-invariant
// ordering); one exact __fdiv_rn per (warp, lane) then atomicMax (composes
// by fl monotonicity).
// ---------------------------------------------------------------------------
#define K1_CHUNK 256

__global__ __launch_bounds__(256) void k_gtmax(
    const float4* __restrict__ anchors,
    const float4* __restrict__ gt,
    int A, int B)
{
    __shared__ float4 sanch[K1_CHUNK];
    __shared__ float  sarea[K1_CHUNK];

    const int lane = threadIdx.x & 31;
    const int warp = threadIdx.x >> 5;

    const int base  = blockIdx.x * K1_CHUNK;
    const int count = min(K1_CHUNK, A - base);

    if (threadIdx.x < count) {
        const float4 a4 = anchors[base + threadIdx.x];
        sanch[threadIdx.x] = a4;
        sarea[threadIdx.x] = box_area(a4);
    }
    __syncthreads();

    for (int b = warp; b < B; b += 8) {
        const float4 g4   = gt[b * 32 + lane];
        const float areag = box_area(g4);

        float bi4 = 0.0f, bS = 1.0f;
#pragma unroll 8
        for (int j = 0; j < count; j++) {
            const float4 a4 = sanch[j];               // warp-broadcast LDS
            const float S      = __fadd_rn(areag, sarea[j]);
            const float inter4 = inter4_of(g4, a4);
            const bool upd = __fmul_rn(inter4, bS) > __fmul_rn(bi4, S);
            bi4 = upd ? inter4 : bi4;
            bS  = upd ? S      : bS;
        }
        const float bi = __fmul_rn(bi4, 0.25f);       // exact unscale (pow2)
        const float h  = __fdiv_rn(bi, __fsub_rn(bS, bi));   // bi=0 -> 0/1 = 0
        atomicMax(&g_highest[b * 32 + lane], __float_as_uint(h));
    }
}

// ---------------------------------------------------------------------------
// Kernel 2: R9 math, but each block owns a 2048-anchor segment (8 tiles of
// 256) for one image: gt staging (incl. the expensive h' divisions) is paid
// ONCE per block instead of once per 256 anchors, and the grid (98 x 8 = 784
// blocks) is fully resident -> single wave, no wave-transition overhead.
// Identical arithmetic and order per anchor => bit-identical outputs.
// ---------------------------------------------------------------------------
#define TILES 8
#define SEG   (TILES * 256)

__global__ __launch_bounds__(256) void k_label(
    const float4* __restrict__ anchors,
    const float4* __restrict__ gt,
    float* __restrict__ out,
    int A, int B)
{
    __shared__ float4 sgt[32];    // gt box
    __shared__ float2 sax[32];    // {area_g, 4*h'}
    __shared__ float  s_h[32];    // exact global max per gt
    __shared__ int    s_anyz;     // any gt with h == 0 -> lq for ALL anchors

    const int b = blockIdx.y;
    if (threadIdx.x < 32) {
        const float4 g4 = gt[b * 32 + threadIdx.x];
        sgt[threadIdx.x] = g4;
        const float h = __uint_as_float(g_highest[b * 32 + threadIdx.x]);
        s_h[threadIdx.x] = h;
        float hp4;
        if (h > 0.0f) {
            const float hl = h * 0.99999f;
            hp4 = (hl / (1.0f + hl)) * 0.99999f * 4.0f;   // threshold for inter4
        } else {
            hp4 = __int_as_float(0x7f800000);  // +inf: band never fires
        }
        sax[threadIdx.x] = make_float2(box_area(g4), hp4);
        const unsigned zb = __ballot_sync(0xffffffffu, h == 0.0f);
        if (threadIdx.x == 0) s_anyz = (zb != 0u);
    }
    __syncthreads();

    const size_t BA  = (size_t)B * (size_t)A;
    const int    seg = blockIdx.x * SEG;

#pragma unroll 1
    for (int t = 0; t < TILES; t++) {
        const int a = seg + t * 256 + threadIdx.x;
        if (a >= A) break;

        const float4 a4   = anchors[a];
        const float areaa = box_area(a4);

        float bi4 = 0.0f, bS = 1.0f;  // running exact-ratio max as (4*inter, S)
        int   bidx = 0;
        float band = -1.0f;           // >= 0 iff some gt may satisfy iou == h

#pragma unroll
        for (int g = 0; g < 32; g++) {
            const float4 g4 = sgt[g];
            const float2 ax = sax[g];
            const float S      = __fadd_rn(ax.x, areaa);
            const float inter4 = inter4_of(g4, a4);

            const bool upd = __fmul_rn(inter4, bS) > __fmul_rn(bi4, S);
            bi4  = upd ? inter4 : bi4;
            bS   = upd ? S      : bS;
            bidx = upd ? g      : bidx;

            band = fmaxf(band, __fmaf_rn(S, -ax.y, inter4));
        }

        bool lq = (s_anyz != 0);
        if (band >= 0.0f) {           // rare (~0.13% of threads)
#pragma unroll 4
            for (int g = 0; g < 32; g++) {
                const float S     = __fadd_rn(sax[g].x, areaa);
                const float inter = inter_of(sgt[g], a4);
                const float uni   = __fsub_rn(S, inter);
                lq = lq || (__fdiv_rn(inter, uni) == s_h[g]);
            }
        }

        const float bi  = __fmul_rn(bi4, 0.25f);      // exact unscale
        const float val = __fdividef(bi, __fsub_rn(bS, bi));
        const float glf = (lq || val >= 0.7f) ? 1.0f : ((val >= 0.3f) ? -1.0f : 0.0f);
        const float olf = (lq || val >= 0.3f) ? 1.0f : ((val >= 0.1f) ? -1.0f : 0.0f);

        const float4 tb4 = sgt[bidx];        // matched gt box (shared argmax)

        const float cx = 0.5f * (a4.x + a4.z);
        const float cy = 0.5f * (a4.y + a4.w);
        const float w  = a4.z - a4.x;
        const float hg = a4.w - a4.y;
        const float nl = cx - tb4.x;
        const float nr = tb4.z - cx;
        const float nt = cy - tb4.y;
        const float nb = tb4.w - cy;

        float cent = 0.0f;
        // sign(n/w) == sign(n) since w,h > 0: in-box test on numerators exact
        if (olf != 0.0f && nl >= 0.0f && nr >= 0.0f && nt >= 0.0f && nb >= 0.0f) {
            const float rx = __fdividef(fminf(nl, nr),
                                        __fmaf_rn(1e-12f, w,  fmaxf(nl, nr)));
            const float ry = __fdividef(fminf(nt, nb),
                                        __fmaf_rn(1e-12f, hg, fmaxf(nt, nb)));
            const float prod = rx * ry;
            cent = (prod > 0.0f) ? sqrt_approx(prod) : 0.0f;
        }

        // layout: [gt_labels B*A][matched B*A*4][obj B*A][centerness B*A]
        const size_t o = (size_t)b * (size_t)A + (size_t)a;
        out[o] = glf;
        reinterpret_cast<float4*>(out + BA)[o] = tb4;
        out[BA * 5 + o] = olf;
        out[BA * 6 + o] = cent;
    }
}

extern "C" void kernel_launch(void* const* d_in, const int* in_sizes, int n_in,
                              void* d_out, int out_size)
{
    const float4* gt      = (const float4*)d_in[0];   // [B,32,4] f32
    const float4* anchors = (const float4*)d_in[1];   // [A,4]    f32
    const int B = in_sizes[0] / (32 * 4);
    const int A = in_sizes[1] / 4;
    float* out = (float*)d_out;

    void* hp = nullptr;
    cudaGetSymbolAddress(&hp, g_highest);
    cudaMemsetAsync(hp, 0, 256 * sizeof(unsigned int), 0);

    dim3 g1((A + K1_CHUNK - 1) / K1_CHUNK, 1);
    k_gtmax<<<g1, 256>>>(anchors, gt, A, B);

    dim3 g2((A + SEG - 1) / SEG, B);
    k_label<<<g2, 256>>>(anchors, gt, out, A, B);
}